// round 4
// baseline (speedup 1.0000x reference)
#include <cuda_runtime.h>

#define BATCH 4
#define CHN   1029
#define HH    80
#define WW    80
#define NROI  1024
#define DD    21
#define PH    7
#define PW    7
#define SCALE 0.0625f

#define LANES_PER_BIN 8
#define BINS_PER_BLOCK 32          // 256 threads / 8 lanes
#define TOTAL_BINS (NROI * DD * PH * PW)   // 1,053,696 = 32 * 32,928

// Warp-cooperative direct PSROI pooling: 8 lanes per output bin.
// Numerics (bin edges) are byte-identical to the validated R3 kernel:
//  - rnd(v) = floor(v + 0.5) with separate rn adds
//  - * SPATIAL_SCALE (1/16) exact
//  - bin = roi * fl(1/7)  (XLA divide-by-constant -> reciprocal multiply)
//  - edges: separate rn mul then rn add (uncontracted)
__global__ __launch_bounds__(256) void psroi_warp_kernel(
    const float* __restrict__ in,       // (4,1029,80,80)
    const float* __restrict__ rois,     // (1024,5)
    float* __restrict__ out) {          // (1024,21,7,7)

    const int tid   = threadIdx.x;
    const int lane8 = tid & (LANES_PER_BIN - 1);
    const int g     = blockIdx.x * BINS_PER_BLOCK + (tid >> 3);  // bin index

    const int pw = g % PW;
    const int ph = (g / PW) % PH;
    const int d  = (g / (PW * PH)) % DD;
    const int n  = g / (PW * PH * DD);

    const float r0 = rois[n * 5 + 0];
    const float r1 = rois[n * 5 + 1];
    const float r2 = rois[n * 5 + 2];
    const float r3 = rois[n * 5 + 3];
    const float r4 = rois[n * 5 + 4];

    const int b = (int)r0;

    const float roi_sw = __fmul_rn(floorf(__fadd_rn(r1, 0.5f)), SCALE);
    const float roi_sh = __fmul_rn(floorf(__fadd_rn(r2, 0.5f)), SCALE);
    const float roi_ew = __fmul_rn(floorf(__fadd_rn(__fadd_rn(r3, 1.0f), 0.5f)), SCALE);
    const float roi_eh = __fmul_rn(floorf(__fadd_rn(__fadd_rn(r4, 1.0f), 0.5f)), SCALE);

    const float roi_w = fmaxf(__fadd_rn(roi_ew, -roi_sw), 0.1f);
    const float roi_h = fmaxf(__fadd_rn(roi_eh, -roi_sh), 0.1f);

    const float inv7 = 1.0f / 7.0f;   // correctly-rounded compile-time constant
    const float bin_w = __fmul_rn(roi_w, inv7);
    const float bin_h = __fmul_rn(roi_h, inv7);

    const float hsf = floorf(__fadd_rn(__fmul_rn((float)ph,       bin_h), roi_sh));
    const float hef = ceilf (__fadd_rn(__fmul_rn((float)(ph + 1), bin_h), roi_sh));
    const float wsf = floorf(__fadd_rn(__fmul_rn((float)pw,       bin_w), roi_sw));
    const float wef = ceilf (__fadd_rn(__fmul_rn((float)(pw + 1), bin_w), roi_sw));

    const int hs = (int)fminf(fmaxf(hsf, 0.0f), (float)HH);
    const int he = (int)fminf(fmaxf(hef, 0.0f), (float)HH);
    const int ws = (int)fminf(fmaxf(wsf, 0.0f), (float)WW);
    const int we = (int)fminf(fmaxf(wef, 0.0f), (float)WW);

    const int bw  = we - ws;
    const int bh  = he - hs;
    const int cnt = bw * bh;

    const int c = (d * PH + ph) * PW + pw;
    const float* __restrict__ plane =
        in + ((size_t)(b * CHN + c)) * (HH * WW) + hs * WW + ws;

    // 8 lanes stride linearly over the bin's cells (row-contiguous addresses).
    float sum = 0.0f;
    for (int i = lane8; i < cnt; i += LANES_PER_BIN) {
        const int dh = i / bw;
        const int dw = i - dh * bw;
        sum += plane[dh * WW + dw];
    }

    // Reduce within the 8-lane group (xor shuffles stay inside the group).
    sum += __shfl_xor_sync(0xffffffffu, sum, 4);
    sum += __shfl_xor_sync(0xffffffffu, sum, 2);
    sum += __shfl_xor_sync(0xffffffffu, sum, 1);

    if (lane8 == 0) {
        out[g] = (cnt > 0) ? __fdiv_rn(sum, (float)cnt) : 0.0f;
    }
}

extern "C" void kernel_launch(void* const* d_in, const int* in_sizes, int n_in,
                              void* d_out, int out_size) {
    const float* input = (const float*)d_in[0];   // (4,1029,80,80) f32
    const float* rois  = (const float*)d_in[1];   // (1024,5) f32
    float* out = (float*)d_out;                   // (1024,21,7,7) f32

    psroi_warp_kernel<<<TOTAL_BINS / BINS_PER_BLOCK, 256>>>(input, rois, out);
}

// round 5
// speedup vs baseline: 1.7191x; 1.7191x over previous
#include <cuda_runtime.h>

#define BATCH 4
#define CHN   1029
#define HH    80
#define WW    80
#define PLANE (HH * WW)
#define NROI  1024
#define PH    7
#define PW    7
#define SCALE 0.0625f

// Per-batch roi lists + per-roi geometry, rebuilt every launch by psroi_prep.
__device__ int    g_cnt[BATCH];
__device__ int    g_list[BATCH][NROI];
__device__ float4 g_geom[NROI];   // x=roi_sw, y=roi_sh, z=bin_w, w=bin_h

// ---------------------------------------------------------------------------
// Prep: one block, 1024 threads. Computes per-roi geometry (validated R3
// numerics) and bins roi indices by batch. Deterministic results: list order
// within a batch is irrelevant (each roi writes its own outputs).
// ---------------------------------------------------------------------------
__global__ __launch_bounds__(NROI) void psroi_prep(const float* __restrict__ rois) {
    const int n = threadIdx.x;
    if (n < BATCH) g_cnt[n] = 0;
    __syncthreads();

    const float r0 = rois[n * 5 + 0];
    const float r1 = rois[n * 5 + 1];
    const float r2 = rois[n * 5 + 2];
    const float r3 = rois[n * 5 + 3];
    const float r4 = rois[n * 5 + 4];

    const int b = (int)r0;

    const float roi_sw = __fmul_rn(floorf(__fadd_rn(r1, 0.5f)), SCALE);
    const float roi_sh = __fmul_rn(floorf(__fadd_rn(r2, 0.5f)), SCALE);
    const float roi_ew = __fmul_rn(floorf(__fadd_rn(__fadd_rn(r3, 1.0f), 0.5f)), SCALE);
    const float roi_eh = __fmul_rn(floorf(__fadd_rn(__fadd_rn(r4, 1.0f), 0.5f)), SCALE);

    const float roi_w = fmaxf(__fadd_rn(roi_ew, -roi_sw), 0.1f);
    const float roi_h = fmaxf(__fadd_rn(roi_eh, -roi_sh), 0.1f);

    const float inv7 = 1.0f / 7.0f;   // correctly-rounded constant (XLA recip)
    const float bin_w = __fmul_rn(roi_w, inv7);
    const float bin_h = __fmul_rn(roi_h, inv7);

    g_geom[n] = make_float4(roi_sw, roi_sh, bin_w, bin_h);

    const int slot = atomicAdd(&g_cnt[b], 1);
    g_list[b][slot] = n;
}

// ---------------------------------------------------------------------------
// Main: one block per (b, c) plane. Plane -> smem (coalesced, read-once),
// then each thread handles one roi's single bin for this channel.
// For channel c: d = c/49, ph = (c%49)/7, pw = c%7; out index = n*1029 + c.
// ---------------------------------------------------------------------------
__global__ __launch_bounds__(256) void psroi_plane_kernel(
    const float* __restrict__ in,     // (4,1029,80,80)
    float* __restrict__ out) {        // (1024,21,7,7) == (1024,1029)

    __shared__ float s[PLANE];        // 25.6 KB

    const int plane = blockIdx.x;     // b*CHN + c
    const int b = plane / CHN;
    const int c = plane - b * CHN;

    // Coalesced 128-bit plane load.
    {
        const float4* __restrict__ src4 =
            reinterpret_cast<const float4*>(in + (size_t)plane * PLANE);
        float4* __restrict__ s4 = reinterpret_cast<float4*>(s);
        #pragma unroll
        for (int i = threadIdx.x; i < PLANE / 4; i += 256) {
            s4[i] = src4[i];
        }
    }
    __syncthreads();

    const int k  = c % (PH * PW);
    const int ph = k / PW;
    const int pw = k - ph * PW;
    const float fph0 = (float)ph,  fph1 = (float)(ph + 1);
    const float fpw0 = (float)pw,  fpw1 = (float)(pw + 1);

    const int cnt_b = g_cnt[b];
    for (int i = threadIdx.x; i < cnt_b; i += 256) {
        const int n = g_list[b][i];
        const float4 gm = g_geom[n];   // x=sw, y=sh, z=bin_w, w=bin_h

        const float hsf = floorf(__fadd_rn(__fmul_rn(fph0, gm.w), gm.y));
        const float hef = ceilf (__fadd_rn(__fmul_rn(fph1, gm.w), gm.y));
        const float wsf = floorf(__fadd_rn(__fmul_rn(fpw0, gm.z), gm.x));
        const float wef = ceilf (__fadd_rn(__fmul_rn(fpw1, gm.z), gm.x));

        const int hs = (int)fminf(fmaxf(hsf, 0.0f), (float)HH);
        const int he = (int)fminf(fmaxf(hef, 0.0f), (float)HH);
        const int ws = (int)fminf(fmaxf(wsf, 0.0f), (float)WW);
        const int we = (int)fminf(fmaxf(wef, 0.0f), (float)WW);

        const int area = (he - hs) * (we - ws);
        float res = 0.0f;
        if (area > 0) {
            float sum = 0.0f;
            for (int h = hs; h < he; ++h) {
                const float* __restrict__ row = s + h * WW;
                float rsum = 0.0f;
                #pragma unroll 4
                for (int w = ws; w < we; ++w) {
                    rsum += row[w];
                }
                sum += rsum;
            }
            res = __fdiv_rn(sum, (float)area);
        }
        out[n * CHN + c] = res;
    }
}

extern "C" void kernel_launch(void* const* d_in, const int* in_sizes, int n_in,
                              void* d_out, int out_size) {
    const float* input = (const float*)d_in[0];   // (4,1029,80,80) f32
    const float* rois  = (const float*)d_in[1];   // (1024,5) f32
    float* out = (float*)d_out;                   // (1024,21,7,7) f32

    psroi_prep<<<1, NROI>>>(rois);
    psroi_plane_kernel<<<BATCH * CHN, 256>>>(input, out);
}

// round 6
// speedup vs baseline: 1.7337x; 1.0085x over previous
#include <cuda_runtime.h>

#define BATCH 4
#define CHN   1029
#define HH    80
#define WW    80
#define PLANE (HH * WW)
#define NROI  1024
#define PH    7
#define PW    7
#define SCALE 0.0625f
#define SP    81          // padded SAT dim / row stride (odd -> conflict-free)

// One kernel, one block per (b,c) plane.
//  Phase 1: coalesced plane load -> smem (input read exactly once).
//  Phase 2: in-smem padded SAT (81x81), column scan then row scan.
//  Phase 3: each thread strides over all 1024 rois; for rois of this batch,
//           compute bin edges (validated R3/XLA numerics) and the bin sum as
//           4 SAT lookups; one coalesced-ish store per roi.
__global__ __launch_bounds__(256) void psroi_sat_plane_kernel(
    const float* __restrict__ in,       // (4,1029,80,80)
    const float* __restrict__ rois,     // (1024,5)
    float* __restrict__ out) {          // (1024,21,7,7) == (1024,1029)

    __shared__ float s[SP][SP];         // 26,244 B padded SAT

    const int tid   = threadIdx.x;
    const int plane = blockIdx.x;       // b*CHN + c
    const int b     = plane / CHN;
    const int c     = plane - b * CHN;

    // ---- Phase 1: load plane (float4 from gmem, data at s[1..80][1..80]) ----
    {
        const float4* __restrict__ src4 =
            reinterpret_cast<const float4*>(in + (size_t)plane * PLANE);
        #pragma unroll
        for (int i = tid; i < PLANE / 4; i += 256) {
            const float4 v = src4[i];
            const int idx = i * 4;
            const int h = idx / WW;          // all 4 elems in same row (80 % 4 == 0)
            const int w = idx - h * WW;
            s[h + 1][w + 1] = v.x;
            s[h + 1][w + 2] = v.y;
            s[h + 1][w + 3] = v.z;
            s[h + 1][w + 4] = v.w;
        }
        if (tid < SP) { s[0][tid] = 0.0f; s[tid][0] = 0.0f; }
    }
    __syncthreads();

    // ---- Phase 2a: cumsum along H (thread = column, lane-consecutive) ----
    if (tid < WW) {
        const int w = tid + 1;
        float acc = 0.0f;
        #pragma unroll 8
        for (int h = 1; h <= HH; ++h) {
            acc = __fadd_rn(acc, s[h][w]);
            s[h][w] = acc;
        }
    }
    __syncthreads();

    // ---- Phase 2b: cumsum along W (thread = row, stride 81 -> no conflicts) ----
    if (tid < HH) {
        const int h = tid + 1;
        float acc = 0.0f;
        #pragma unroll 8
        for (int w = 1; w <= WW; ++w) {
            acc = __fadd_rn(acc, s[h][w]);
            s[h][w] = acc;
        }
    }
    __syncthreads();

    // ---- Phase 3: pooling for this channel's fixed (ph, pw) ----
    const int k  = c % (PH * PW);
    const int ph = k / PW;
    const int pw = k - ph * PW;
    const float fph0 = (float)ph, fph1 = (float)(ph + 1);
    const float fpw0 = (float)pw, fpw1 = (float)(pw + 1);
    const float inv7 = 1.0f / 7.0f;   // correctly-rounded (XLA div->recip)

    #pragma unroll
    for (int n = tid; n < NROI; n += 256) {
        const float r0 = rois[n * 5 + 0];
        if ((int)r0 != b) continue;

        const float r1 = rois[n * 5 + 1];
        const float r2 = rois[n * 5 + 2];
        const float r3 = rois[n * 5 + 3];
        const float r4 = rois[n * 5 + 4];

        // Validated numerics: rnd = floor(v+0.5), *1/16 exact, *fl(1/7),
        // uncontracted rn mul+add for edges.
        const float roi_sw = __fmul_rn(floorf(__fadd_rn(r1, 0.5f)), SCALE);
        const float roi_sh = __fmul_rn(floorf(__fadd_rn(r2, 0.5f)), SCALE);
        const float roi_ew = __fmul_rn(floorf(__fadd_rn(__fadd_rn(r3, 1.0f), 0.5f)), SCALE);
        const float roi_eh = __fmul_rn(floorf(__fadd_rn(__fadd_rn(r4, 1.0f), 0.5f)), SCALE);

        const float roi_w = fmaxf(__fadd_rn(roi_ew, -roi_sw), 0.1f);
        const float roi_h = fmaxf(__fadd_rn(roi_eh, -roi_sh), 0.1f);
        const float bin_w = __fmul_rn(roi_w, inv7);
        const float bin_h = __fmul_rn(roi_h, inv7);

        const float hsf = floorf(__fadd_rn(__fmul_rn(fph0, bin_h), roi_sh));
        const float hef = ceilf (__fadd_rn(__fmul_rn(fph1, bin_h), roi_sh));
        const float wsf = floorf(__fadd_rn(__fmul_rn(fpw0, bin_w), roi_sw));
        const float wef = ceilf (__fadd_rn(__fmul_rn(fpw1, bin_w), roi_sw));

        const int hs = (int)fminf(fmaxf(hsf, 0.0f), (float)HH);
        const int he = (int)fminf(fmaxf(hef, 0.0f), (float)HH);
        const int ws = (int)fminf(fmaxf(wsf, 0.0f), (float)WW);
        const int we = (int)fminf(fmaxf(wef, 0.0f), (float)WW);

        const int area = (he - hs) * (we - ws);
        float res = 0.0f;
        if (area > 0) {
            // Same combination order as the reference.
            const float ssum = __fadd_rn(__fadd_rn(__fadd_rn(
                s[he][we], -s[hs][we]), -s[he][ws]), s[hs][ws]);
            res = __fdiv_rn(ssum, (float)area);
        }
        out[n * CHN + c] = res;
    }
}

extern "C" void kernel_launch(void* const* d_in, const int* in_sizes, int n_in,
                              void* d_out, int out_size) {
    const float* input = (const float*)d_in[0];   // (4,1029,80,80) f32
    const float* rois  = (const float*)d_in[1];   // (1024,5) f32
    float* out = (float*)d_out;                   // (1024,21,7,7) f32

    psroi_sat_plane_kernel<<<BATCH * CHN, 256>>>(input, rois, out);
}

// round 7
// speedup vs baseline: 1.7765x; 1.0247x over previous
#include <cuda_runtime.h>

#define BATCH 4
#define CHN   1029
#define HH    80
#define WW    80
#define PLANE (HH * WW)
#define NROI  1024
#define PH    7
#define PW    7
#define SCALE 0.0625f
#define SP    81          // padded SAT dim / row stride (odd -> conflict-free)

// One kernel, one block per (b,c) plane.
//  Phase A: fused gmem-load + H-cumsum. Thread = column w; reads
//           in[h*80+w] (lane-consecutive -> coalesced), accumulates in a
//           register, stores only the running sum to smem. No staging pass.
//  Phase B: W-cumsum in smem (thread = row, stride 81 -> conflict-free).
//  Phase C: each thread strides over the 1024 rois; for rois of this batch,
//           bin edges via the validated XLA numerics, bin sum = 4 SAT LDS.
__global__ __launch_bounds__(256) void psroi_sat_fused_kernel(
    const float* __restrict__ in,       // (4,1029,80,80)
    const float* __restrict__ rois,     // (1024,5)
    float* __restrict__ out) {          // (1024,21,7,7) == (1024,1029)

    __shared__ float s[SP][SP];         // 26,244 B padded SAT

    const int tid   = threadIdx.x;
    const int plane = blockIdx.x;       // b*CHN + c
    const int b     = plane / CHN;
    const int c     = plane - b * CHN;

    // ---- zero pad row/col ----
    if (tid < SP)      s[0][tid] = 0.0f;
    else if (tid < 2 * SP && tid - SP > 0) s[tid - SP][0] = 0.0f;

    // ---- Phase A: fused load + cumsum along H ----
    if (tid < WW) {
        const float* __restrict__ col = in + (size_t)plane * PLANE + tid;
        float acc = 0.0f;
        #pragma unroll 8
        for (int h = 0; h < HH; ++h) {
            acc = __fadd_rn(acc, col[h * WW]);   // coalesced across lanes
            s[h + 1][tid + 1] = acc;
        }
    }
    __syncthreads();

    // ---- Phase B: cumsum along W (thread = row, stride 81 -> no conflicts) ----
    if (tid < HH) {
        const int h = tid + 1;
        float acc = 0.0f;
        #pragma unroll 8
        for (int w = 1; w <= WW; ++w) {
            acc = __fadd_rn(acc, s[h][w]);
            s[h][w] = acc;
        }
    }
    __syncthreads();

    // ---- Phase C: pooling for this channel's fixed (ph, pw) ----
    const int k  = c % (PH * PW);
    const int ph = k / PW;
    const int pw = k - ph * PW;
    const float fph0 = (float)ph, fph1 = (float)(ph + 1);
    const float fpw0 = (float)pw, fpw1 = (float)(pw + 1);
    const float inv7 = 1.0f / 7.0f;   // correctly-rounded (XLA div->recip)

    #pragma unroll
    for (int n = tid; n < NROI; n += 256) {
        const float r0 = rois[n * 5 + 0];
        if ((int)r0 != b) continue;

        const float r1 = rois[n * 5 + 1];
        const float r2 = rois[n * 5 + 2];
        const float r3 = rois[n * 5 + 3];
        const float r4 = rois[n * 5 + 4];

        // Validated numerics: rnd = floor(v+0.5), *1/16 exact, *fl(1/7),
        // uncontracted rn mul+add for edges.
        const float roi_sw = __fmul_rn(floorf(__fadd_rn(r1, 0.5f)), SCALE);
        const float roi_sh = __fmul_rn(floorf(__fadd_rn(r2, 0.5f)), SCALE);
        const float roi_ew = __fmul_rn(floorf(__fadd_rn(__fadd_rn(r3, 1.0f), 0.5f)), SCALE);
        const float roi_eh = __fmul_rn(floorf(__fadd_rn(__fadd_rn(r4, 1.0f), 0.5f)), SCALE);

        const float roi_w = fmaxf(__fadd_rn(roi_ew, -roi_sw), 0.1f);
        const float roi_h = fmaxf(__fadd_rn(roi_eh, -roi_sh), 0.1f);
        const float bin_w = __fmul_rn(roi_w, inv7);
        const float bin_h = __fmul_rn(roi_h, inv7);

        const float hsf = floorf(__fadd_rn(__fmul_rn(fph0, bin_h), roi_sh));
        const float hef = ceilf (__fadd_rn(__fmul_rn(fph1, bin_h), roi_sh));
        const float wsf = floorf(__fadd_rn(__fmul_rn(fpw0, bin_w), roi_sw));
        const float wef = ceilf (__fadd_rn(__fmul_rn(fpw1, bin_w), roi_sw));

        const int hs = (int)fminf(fmaxf(hsf, 0.0f), (float)HH);
        const int he = (int)fminf(fmaxf(hef, 0.0f), (float)HH);
        const int ws = (int)fminf(fmaxf(wsf, 0.0f), (float)WW);
        const int we = (int)fminf(fmaxf(wef, 0.0f), (float)WW);

        const int area = (he - hs) * (we - ws);
        float res = 0.0f;
        if (area > 0) {
            // Same combination order as the reference.
            const float ssum = __fadd_rn(__fadd_rn(__fadd_rn(
                s[he][we], -s[hs][we]), -s[he][ws]), s[hs][ws]);
            res = __fdiv_rn(ssum, (float)area);
        }
        out[n * CHN + c] = res;
    }
}

extern "C" void kernel_launch(void* const* d_in, const int* in_sizes, int n_in,
                              void* d_out, int out_size) {
    const float* input = (const float*)d_in[0];   // (4,1029,80,80) f32
    const float* rois  = (const float*)d_in[1];   // (1024,5) f32
    float* out = (float*)d_out;                   // (1024,21,7,7) f32

    psroi_sat_fused_kernel<<<BATCH * CHN, 256>>>(input, rois, out);
}

// round 8
// speedup vs baseline: 2.0977x; 1.1808x over previous
#include <cuda_runtime.h>

#define BATCH 4
#define CHN   1029
#define HH    80
#define WW    80
#define PLANE (HH * WW)
#define NROI  1024
#define PH    7
#define PW    7
#define SCALE 0.0625f
#define SP    81          // padded SAT row stride (odd -> conflict-free LDS)
#define SEG   20          // 4 segments of 20 cover 80
#define NSEG  4
#define NT    320         // 4*80 threads

// One block per (b,c) plane. Two-level (segmented) SAT build with
// register-resident segments to kill serial-chain latency, then pooling.
__global__ __launch_bounds__(NT) void psroi_sat_seg_kernel(
    const float* __restrict__ in,       // (4,1029,80,80)
    const float* __restrict__ rois,     // (1024,5)
    float* __restrict__ out) {          // (1024,21,7,7) == (1024,1029)

    __shared__ float s[SP][SP];         // padded SAT, pad row 0 / col 0
    __shared__ float auxA[NSEG][80];    // column-segment totals (H scan)
    __shared__ float auxB[NSEG][80];    // row-segment totals (W scan)

    const int tid   = threadIdx.x;
    const int plane = blockIdx.x;       // b*CHN + c
    const int b     = plane / CHN;
    const int c     = plane - b * CHN;

    // zero pad row / pad col
    if (tid < SP) s[0][tid] = 0.0f;
    else if (tid < SP + HH) s[tid - SP + 1][0] = 0.0f;

    // ---- Phase A: H-cumsum, thread = (h-segment sa, column w) ----
    {
        const int sa = tid / 80;        // 0..3
        const int w  = tid - sa * 80;   // 0..79
        const float* __restrict__ col = in + (size_t)plane * PLANE + (size_t)(sa * SEG) * WW + w;

        float v[SEG];
        #pragma unroll
        for (int i = 0; i < SEG; ++i) v[i] = col[i * WW];   // 20 loads in flight
        #pragma unroll
        for (int i = 1; i < SEG; ++i) v[i] = __fadd_rn(v[i], v[i - 1]);

        auxA[sa][w] = v[SEG - 1];
        __syncthreads();

        float p = 0.0f;
        #pragma unroll
        for (int j = 0; j < NSEG - 1; ++j)
            if (j < sa) p = __fadd_rn(p, auxA[j][w]);

        #pragma unroll
        for (int i = 0; i < SEG; ++i)
            s[sa * SEG + i + 1][w + 1] = __fadd_rn(v[i], p);
    }
    __syncthreads();

    // ---- Phase B: W-cumsum, thread = (w-segment cs, row r) ----
    {
        const int cs = tid / 80;        // 0..3
        const int r  = tid - cs * 80;   // 0..79
        float* __restrict__ row = &s[r + 1][cs * SEG + 1];

        float v[SEG];
        #pragma unroll
        for (int i = 0; i < SEG; ++i) v[i] = row[i];        // independent LDS
        #pragma unroll
        for (int i = 1; i < SEG; ++i) v[i] = __fadd_rn(v[i], v[i - 1]);

        auxB[cs][r] = v[SEG - 1];
        __syncthreads();

        float p = 0.0f;
        #pragma unroll
        for (int j = 0; j < NSEG - 1; ++j)
            if (j < cs) p = __fadd_rn(p, auxB[j][r]);

        #pragma unroll
        for (int i = 0; i < SEG; ++i)
            row[i] = __fadd_rn(v[i], p);
    }
    __syncthreads();

    // ---- Phase C: pooling, fixed (ph, pw) for this channel ----
    const int k  = c % (PH * PW);
    const int ph = k / PW;
    const int pw = k - ph * PW;
    const float fph0 = (float)ph, fph1 = (float)(ph + 1);
    const float fpw0 = (float)pw, fpw1 = (float)(pw + 1);
    const float inv7 = 1.0f / 7.0f;   // correctly-rounded (XLA div->recip)

    for (int n = tid; n < NROI; n += NT) {
        const float r0 = rois[n * 5 + 0];
        if ((int)r0 != b) continue;

        const float r1 = rois[n * 5 + 1];
        const float r2 = rois[n * 5 + 2];
        const float r3 = rois[n * 5 + 3];
        const float r4 = rois[n * 5 + 4];

        // Validated numerics: rnd = floor(v+0.5), *1/16 exact, *fl(1/7),
        // uncontracted rn mul+add for edges.
        const float roi_sw = __fmul_rn(floorf(__fadd_rn(r1, 0.5f)), SCALE);
        const float roi_sh = __fmul_rn(floorf(__fadd_rn(r2, 0.5f)), SCALE);
        const float roi_ew = __fmul_rn(floorf(__fadd_rn(__fadd_rn(r3, 1.0f), 0.5f)), SCALE);
        const float roi_eh = __fmul_rn(floorf(__fadd_rn(__fadd_rn(r4, 1.0f), 0.5f)), SCALE);

        const float roi_w = fmaxf(__fadd_rn(roi_ew, -roi_sw), 0.1f);
        const float roi_h = fmaxf(__fadd_rn(roi_eh, -roi_sh), 0.1f);
        const float bin_w = __fmul_rn(roi_w, inv7);
        const float bin_h = __fmul_rn(roi_h, inv7);

        const float hsf = floorf(__fadd_rn(__fmul_rn(fph0, bin_h), roi_sh));
        const float hef = ceilf (__fadd_rn(__fmul_rn(fph1, bin_h), roi_sh));
        const float wsf = floorf(__fadd_rn(__fmul_rn(fpw0, bin_w), roi_sw));
        const float wef = ceilf (__fadd_rn(__fmul_rn(fpw1, bin_w), roi_sw));

        const int hs = (int)fminf(fmaxf(hsf, 0.0f), (float)HH);
        const int he = (int)fminf(fmaxf(hef, 0.0f), (float)HH);
        const int ws = (int)fminf(fmaxf(wsf, 0.0f), (float)WW);
        const int we = (int)fminf(fmaxf(wef, 0.0f), (float)WW);

        const int area = (he - hs) * (we - ws);
        float res = 0.0f;
        if (area > 0) {
            const float ssum = __fadd_rn(__fadd_rn(__fadd_rn(
                s[he][we], -s[hs][we]), -s[he][ws]), s[hs][ws]);
            res = __fdiv_rn(ssum, (float)area);
        }
        out[n * CHN + c] = res;
    }
}

extern "C" void kernel_launch(void* const* d_in, const int* in_sizes, int n_in,
                              void* d_out, int out_size) {
    const float* input = (const float*)d_in[0];   // (4,1029,80,80) f32
    const float* rois  = (const float*)d_in[1];   // (1024,5) f32
    float* out = (float*)d_out;                   // (1024,21,7,7) f32

    psroi_sat_seg_kernel<<<BATCH * CHN, NT>>>(input, rois, out);
}